// round 16
// baseline (speedup 1.0000x reference)
#include <cuda_runtime.h>
#include <cuda_bf16.h>
#include <cuda_fp16.h>
#include <cstdint>

// ---------------- constants ----------------
#define NN      50000
#define MAXE    2000000
#define HEADS   4
#define HC      256          // HEADS*HID
#define OUTC    128
#define KDIM    256
#define NB_SCAN ((NN + 255) / 256)
// half-split at a 128-row boundary
#define NH1     25088
#define NH2     (NN - NH1)        // 24912
#define BX1     (NH1 / 128)       // 196
#define BX2     ((NN + 127) / 128 - BX1)  // 195

// ---------------- device scratch ----------------
__device__ __half   g_projA[(size_t)NN * HC];
__device__ __half   g_projB[(size_t)NN * HC];
__device__ float    g_alsA[NN * HEADS], g_aldA[NN * HEADS];
__device__ float    g_alsB[NN * HEADS], g_aldB[NN * HEADS];
__device__ float    g_als2[NN],         g_ald2[NN];
__device__ int      g_src [MAXE];
__device__ int      g_dst [MAXE];
__device__ int      g_ssrc[MAXE];
__device__ int      g_cnt [NN];
__device__ int      g_tmp [NN];
__device__ int      g_bsum[256];
__device__ int      g_boff[256];
__device__ int      g_cursor[NN];
__device__ int      g_rowptr[NN + 1];
__device__ int      g_is64;
__device__ __nv_bfloat16 g_ahi[(size_t)NN * KDIM];
__device__ __nv_bfloat16 g_alo[(size_t)NN * KDIM];
__device__ __nv_bfloat16 g_w0hi[KDIM * HC],  g_w0lo[KDIM * HC];
__device__ __nv_bfloat16 g_w1hi[KDIM * HC],  g_w1lo[KDIM * HC];
__device__ __nv_bfloat16 g_wchi[KDIM * 256], g_wclo[KDIM * 256];  // [W2 | Wl]

// ---------------- helpers ----------------
__device__ __forceinline__ float lrelu(float v) { return v > 0.f ? v : 0.2f * v; }

__device__ __forceinline__ uint32_t s2u(const void* p) {
    uint32_t a;
    asm("{ .reg .u64 t; cvta.to.shared.u64 t, %1; cvt.u32.u64 %0, t; }" : "=r"(a) : "l"(p));
    return a;
}

__device__ __forceinline__ void cpa16(uint32_t dst, const void* src, int ssize) {
    asm volatile("cp.async.cg.shared.global [%0], [%1], 16, %2;"
                 :: "r"(dst), "l"(src), "r"(ssize));
}

#define LDM4(d, addr) \
    asm volatile("ldmatrix.sync.aligned.m8n8.x4.shared.b16 {%0,%1,%2,%3}, [%4];" \
        : "=r"((d)[0]), "=r"((d)[1]), "=r"((d)[2]), "=r"((d)[3]) : "r"(addr))

#define MMA_BF16(c, a, b0, b1) \
    asm volatile("mma.sync.aligned.m16n8k16.row.col.f32.bf16.bf16.f32 " \
        "{%0,%1,%2,%3}, {%4,%5,%6,%7}, {%8,%9}, {%0,%1,%2,%3};" \
        : "+f"((c)[0]), "+f"((c)[1]), "+f"((c)[2]), "+f"((c)[3]) \
        : "r"((a)[0]), "r"((a)[1]), "r"((a)[2]), "r"((a)[3]), "r"(b0), "r"(b1))

// ---------------- edge index prep ----------------
__global__ void probe_kernel(const int* p32, int nchk) {
    __shared__ int cnt;
    if (threadIdx.x == 0) cnt = 0;
    __syncthreads();
    int z = 0;
    for (int k = threadIdx.x; k < nchk; k += 256)
        if (p32[2 * k + 1] == 0) z++;
    atomicAdd(&cnt, z);
    __syncthreads();
    if (threadIdx.x == 0) g_is64 = (cnt * 2 > nchk) ? 1 : 0;
}

__global__ void convert_hist(const void* ei, int E) {
    int e = blockIdx.x * blockDim.x + threadIdx.x;
    if (e >= E || e >= MAXE) return;
    int s, d;
    if (g_is64) {
        const long long* p = (const long long*)ei;
        s = (int)p[e];
        d = (int)p[(size_t)E + e];
    } else {
        const int* p = (const int*)ei;
        s = p[e];
        d = p[E + e];
    }
    g_src[e] = s;
    g_dst[e] = d;
    atomicAdd(&g_cnt[d], 1);
}

// ---------------- 3-phase exclusive scan ----------------
__global__ void scanA() {
    int i = blockIdx.x * 256 + threadIdx.x;
    int lane = threadIdx.x & 31, warp = threadIdx.x >> 5;
    int v = (i < NN) ? g_cnt[i] : 0;
    int x = v;
#pragma unroll
    for (int off = 1; off < 32; off <<= 1) {
        int t = __shfl_up_sync(0xffffffffu, x, off);
        if (lane >= off) x += t;
    }
    __shared__ int ws[8];
    if (lane == 31) ws[warp] = x;
    __syncthreads();
    if (threadIdx.x == 0) {
        int run = 0;
#pragma unroll
        for (int j = 0; j < 8; j++) { int t = ws[j]; ws[j] = run; run += t; }
        g_bsum[blockIdx.x] = run;
    }
    __syncthreads();
    if (i < NN) g_tmp[i] = x - v + ws[warp];
}

__global__ void scanB(int nb) {
    int tid = threadIdx.x, lane = tid & 31, warp = tid >> 5;
    int v = (tid < nb) ? g_bsum[tid] : 0;
    int x = v;
#pragma unroll
    for (int off = 1; off < 32; off <<= 1) {
        int t = __shfl_up_sync(0xffffffffu, x, off);
        if (lane >= off) x += t;
    }
    __shared__ int ws[8];
    if (lane == 31) ws[warp] = x;
    __syncthreads();
    if (tid == 0) {
        int run = 0;
#pragma unroll
        for (int j = 0; j < 8; j++) { int t = ws[j]; ws[j] = run; run += t; }
        g_rowptr[NN] = run;
    }
    __syncthreads();
    g_boff[tid] = x - v + ws[warp];
}

__global__ void scanC() {
    int i = blockIdx.x * 256 + threadIdx.x;
    if (i < NN) {
        int r = g_tmp[i] + g_boff[blockIdx.x];
        g_rowptr[i] = r;
        g_cursor[i] = r;
    }
}

__global__ void scatter_kernel(int E) {
    int e = blockIdx.x * blockDim.x + threadIdx.x;
    if (e >= E || e >= MAXE) return;
    int pos = atomicAdd(&g_cursor[g_dst[e]], 1);
    g_ssrc[pos] = g_src[e];
}

// ---------------- bf16 hi/lo split (layer-0 input only) ----------------
__global__ void split_act(const float* __restrict__ in, __nv_bfloat16* __restrict__ hi,
                          __nv_bfloat16* __restrict__ lo, int total4) {
    int i = blockIdx.x * blockDim.x + threadIdx.x;
    if (i >= total4) return;
    float4 v = ((const float4*)in)[i];
    float vv[4] = {v.x, v.y, v.z, v.w};
    __nv_bfloat16 h[4], l[4];
#pragma unroll
    for (int j = 0; j < 4; j++) {
        h[j] = __float2bfloat16(vv[j]);
        l[j] = __float2bfloat16(vv[j] - __bfloat162float(h[j]));
    }
    ((__nv_bfloat162*)hi)[2 * i]     = __nv_bfloat162(h[0], h[1]);
    ((__nv_bfloat162*)hi)[2 * i + 1] = __nv_bfloat162(h[2], h[3]);
    ((__nv_bfloat162*)lo)[2 * i]     = __nv_bfloat162(l[0], l[1]);
    ((__nv_bfloat162*)lo)[2 * i + 1] = __nv_bfloat162(l[2], l[3]);
}

// ---------------- merged weight transpose + split ----------------
__global__ void wsplit_all(const float* __restrict__ W0, const float* __restrict__ W1,
                           const float* __restrict__ W2, const float* __restrict__ Wl) {
    int idx = blockIdx.x * blockDim.x + threadIdx.x;
    if (idx >= 196608) return;
    const float* W;
    __nv_bfloat16 *hi, *lo;
    int local, Nn;
    if (idx < 65536)       { W = W0; hi = g_w0hi; lo = g_w0lo; local = idx; Nn = 256; }
    else if (idx < 131072) { W = W1; hi = g_w1hi; lo = g_w1lo; local = idx - 65536; Nn = 256; }
    else if (idx < 163840) { W = W2; hi = g_wchi; lo = g_wclo; local = idx - 131072; Nn = 128; }
    else                   { W = Wl; hi = g_wchi + 128 * 256; lo = g_wclo + 128 * 256;
                             local = idx - 163840; Nn = 128; }
    int n = local >> 8, k = local & 255;
    float v = W[(size_t)k * Nn + n];
    __nv_bfloat16 h = __float2bfloat16(v);
    hi[local] = h;
    lo[local] = __float2bfloat16(v - __bfloat162float(h));
}

// ---------------- HMMA split-bf16 GEMM, 2-stage cp.async pipeline ----------------
// Output C is fp16 (gather buffer); attention logits use the fp32 accumulators.
#define STG 43008
__global__ void __launch_bounds__(256, 2) gemm_mma(
    const __nv_bfloat16* __restrict__ Ahi, const __nv_bfloat16* __restrict__ Alo,
    const __nv_bfloat16* __restrict__ Bhi, const __nv_bfloat16* __restrict__ Blo,
    __half* __restrict__ C, int M, int Nn,
    int lmode, const float* __restrict__ a_s, const float* __restrict__ a_d,
    float* __restrict__ als, float* __restrict__ ald, int bx0)
{
    extern __shared__ __align__(16) char smem[];
    float* red_ss = (float*)(smem + 2 * STG);
    float* red_sd = red_ss + 128;
    constexpr int A_HI = 0;
    constexpr int A_LO = 14336;
    constexpr int B_HI = 28672;
    constexpr int B_LO = 35840;

    const int tid  = threadIdx.x;
    const int lane = tid & 31;
    const int wid  = tid >> 5;
    const int warpRow = wid & 3;
    const int warpCol = wid >> 2;
    const int rowBase = (blockIdx.x + bx0) * 128;
    const int colBase = blockIdx.y * 64;

    float acc[2][4][4];
#pragma unroll
    for (int i = 0; i < 2; i++)
#pragma unroll
        for (int j = 0; j < 4; j++)
#pragma unroll
            for (int q = 0; q < 4; q++) acc[i][j][q] = 0.f;

    const uint32_t sb = s2u(smem);
    uint32_t aAdrH[2], aAdrL[2];
#pragma unroll
    for (int m16 = 0; m16 < 2; m16++) {
        uint32_t r = warpRow * 32 + m16 * 16 + (lane & 15);
        uint32_t cb = ((lane >> 4) * 8) * 2;
        aAdrH[m16] = sb + A_HI + r * 112 + cb;
        aAdrL[m16] = sb + A_LO + r * 112 + cb;
    }
    uint32_t bAdrH[2], bAdrL[2];
#pragma unroll
    for (int nbp = 0; nbp < 2; nbp++) {
        uint32_t r = warpCol * 32 + nbp * 16 + ((lane >> 4) << 3) + (lane & 7);
        uint32_t cb = (((lane >> 3) & 1) * 8) * 2;
        bAdrH[nbp] = sb + B_HI + r * 112 + cb;
        bAdrL[nbp] = sb + B_LO + r * 112 + cb;
    }

    const int ar0 = tid >> 2, aseg = tid & 3;
    const int br0 = tid >> 2;

    auto prefetch = [&](int c) {
        const uint32_t base = sb + (uint32_t)(c & 1) * STG;
        const int k0 = c * 32;
#pragma unroll
        for (int it = 0; it < 2; it++) {
            int r = ar0 + it * 64;
            int gr = rowBase + r;
            int ok = (gr < M) ? 16 : 0;
            size_t g = (size_t)(ok ? gr : 0) * KDIM + k0 + aseg * 8;
            cpa16(base + A_HI + r * 112 + aseg * 16, Ahi + g, ok);
            cpa16(base + A_LO + r * 112 + aseg * 16, Alo + g, ok);
        }
        {
            size_t g = (size_t)(colBase + br0) * KDIM + k0 + aseg * 8;
            cpa16(base + B_HI + br0 * 112 + aseg * 16, Bhi + g, 16);
            cpa16(base + B_LO + br0 * 112 + aseg * 16, Blo + g, 16);
        }
        asm volatile("cp.async.commit_group;");
    };

    prefetch(0);
    for (int c = 0; c < 8; c++) {
        if (c < 7) {
            prefetch(c + 1);
            asm volatile("cp.async.wait_group 1;");
        } else {
            asm volatile("cp.async.wait_group 0;");
        }
        __syncthreads();
        const uint32_t so = (uint32_t)(c & 1) * STG;
#pragma unroll
        for (int kk = 0; kk < 2; kk++) {
            const uint32_t kb = so + kk * 32;
            uint32_t ah[2][4], al[2][4], bh[2][4], bl[2][4];
            LDM4(ah[0], aAdrH[0] + kb);
            LDM4(ah[1], aAdrH[1] + kb);
            LDM4(al[0], aAdrL[0] + kb);
            LDM4(al[1], aAdrL[1] + kb);
            LDM4(bh[0], bAdrH[0] + kb);
            LDM4(bh[1], bAdrH[1] + kb);
            LDM4(bl[0], bAdrL[0] + kb);
            LDM4(bl[1], bAdrL[1] + kb);
#pragma unroll
            for (int m16 = 0; m16 < 2; m16++) {
#pragma unroll
                for (int nb = 0; nb < 4; nb++) {
                    const int p = nb >> 1, q = (nb & 1) * 2;
                    MMA_BF16(acc[m16][nb], ah[m16], bh[p][q], bh[p][q + 1]);
                    MMA_BF16(acc[m16][nb], ah[m16], bl[p][q], bl[p][q + 1]);
                    MMA_BF16(acc[m16][nb], al[m16], bh[p][q], bh[p][q + 1]);
                }
            }
        }
        __syncthreads();
    }

    // ---- store C (fp16) ----
#pragma unroll
    for (int m16 = 0; m16 < 2; m16++) {
        int r0 = rowBase + warpRow * 32 + m16 * 16 + (lane >> 2);
#pragma unroll
        for (int nb = 0; nb < 4; nb++) {
            int col = colBase + warpCol * 32 + nb * 8 + (lane & 3) * 2;
            if (r0 < M)
                *(__half2*)(C + (size_t)r0 * Nn + col) =
                    __floats2half2_rn(acc[m16][nb][0], acc[m16][nb][1]);
            if (r0 + 8 < M)
                *(__half2*)(C + (size_t)(r0 + 8) * Nn + col) =
                    __floats2half2_rn(acc[m16][nb][2], acc[m16][nb][3]);
        }
    }

    // ---- fused attention logits (from fp32 accumulators; exact) ----
    if (lmode == 1 || (lmode == 2 && blockIdx.y < 2)) {
        const int y = blockIdx.y;
        float pss[2][2] = {{0.f, 0.f}, {0.f, 0.f}};
        float psd[2][2] = {{0.f, 0.f}, {0.f, 0.f}};
#pragma unroll
        for (int m16 = 0; m16 < 2; m16++) {
#pragma unroll
            for (int nb = 0; nb < 4; nb++) {
                int cl = warpCol * 32 + nb * 8 + (lane & 3) * 2;
                float s0 = __ldg(a_s + y * 64 + cl), s1 = __ldg(a_s + y * 64 + cl + 1);
                float d0 = __ldg(a_d + y * 64 + cl), d1 = __ldg(a_d + y * 64 + cl + 1);
                pss[m16][0] += acc[m16][nb][0] * s0 + acc[m16][nb][1] * s1;
                psd[m16][0] += acc[m16][nb][0] * d0 + acc[m16][nb][1] * d1;
                pss[m16][1] += acc[m16][nb][2] * s0 + acc[m16][nb][3] * s1;
                psd[m16][1] += acc[m16][nb][2] * d0 + acc[m16][nb][3] * d1;
            }
        }
#pragma unroll
        for (int m16 = 0; m16 < 2; m16++)
#pragma unroll
            for (int hh = 0; hh < 2; hh++) {
                pss[m16][hh] += __shfl_xor_sync(0xffffffffu, pss[m16][hh], 1);
                pss[m16][hh] += __shfl_xor_sync(0xffffffffu, pss[m16][hh], 2);
                psd[m16][hh] += __shfl_xor_sync(0xffffffffu, psd[m16][hh], 1);
                psd[m16][hh] += __shfl_xor_sync(0xffffffffu, psd[m16][hh], 2);
            }
        if (warpCol == 0 && (lane & 3) == 0) {
#pragma unroll
            for (int m16 = 0; m16 < 2; m16++)
#pragma unroll
                for (int hh = 0; hh < 2; hh++) {
                    int rb = warpRow * 32 + m16 * 16 + hh * 8 + (lane >> 2);
                    red_ss[rb] = pss[m16][hh];
                    red_sd[rb] = psd[m16][hh];
                }
        }
        __syncthreads();
        if (warpCol == 1 && (lane & 3) == 0) {
#pragma unroll
            for (int m16 = 0; m16 < 2; m16++)
#pragma unroll
                for (int hh = 0; hh < 2; hh++) {
                    int rb = warpRow * 32 + m16 * 16 + hh * 8 + (lane >> 2);
                    int row = rowBase + rb;
                    if (row < M) {
                        float S = red_ss[rb] + pss[m16][hh];
                        float D = red_sd[rb] + psd[m16][hh];
                        if (lmode == 1) {
                            als[row * 4 + y] = S;
                            ald[row * 4 + y] = D;
                        } else {
                            atomicAdd(&als[row], S);
                            atomicAdd(&ald[row], D);
                        }
                    }
                }
        }
    }
}

// ---------------- fused CSR aggregation, H=4, 256 ch: warp per dst (range) --------
// 2-edge unrolled software pipeline: two independent load chains in flight.
__global__ void gat_agg256(const __half* __restrict__ proj,
                           const float* __restrict__ als, const float* __restrict__ ald,
                           const float* __restrict__ bias,
                           const __nv_bfloat16* __restrict__ reshi,
                           const __nv_bfloat16* __restrict__ reslo,
                           __nv_bfloat16* __restrict__ hi, __nv_bfloat16* __restrict__ lo,
                           int d0, int nd) {
    int w = (blockIdx.x * blockDim.x + threadIdx.x) >> 5;
    if (w >= nd) return;
    const int lane = threadIdx.x & 31;
    const int d = d0 + w;
    const float aldl = (lane < 4) ? ald[d * 4 + lane] : 0.f;

    float wt = 0.f, sden = 0.f;
    if (lane < 4) {
        wt = __expf(lrelu(als[d * 4 + lane] + aldl));
        sden = wt;
    }
    float wh = __shfl_sync(0xffffffffu, wt, lane >> 3);

    const uint4* pr = (const uint4*)proj;      // 32 uint4 per row (256 halfs)
    float o[8];
    {
        uint4 pv = pr[(size_t)d * 32 + lane];
        const __half2* ph = (const __half2*)&pv;
#pragma unroll
        for (int q = 0; q < 4; q++) {
            float2 f = __half22float2(ph[q]);
            o[2 * q]     = wh * f.x;
            o[2 * q + 1] = wh * f.y;
        }
    }
    const int jb = g_rowptr[d], je = g_rowptr[d + 1];
    // pipeline prologue: two edges in flight
    float aEv = 0.f, aFv = 0.f;
    uint4 pE = make_uint4(0, 0, 0, 0), pF = pE;
    if (jb < je) {
        int s = g_ssrc[jb];
        if (lane < 4) aEv = als[s * 4 + lane];
        pE = pr[(size_t)s * 32 + lane];
    }
    if (jb + 1 < je) {
        int s = g_ssrc[jb + 1];
        if (lane < 4) aFv = als[s * 4 + lane];
        pF = pr[(size_t)s * 32 + lane];
    }
    for (int j = jb; j < je; j += 2) {
        // prefetch edges j+2, j+3
        float aE2 = 0.f, aF2 = 0.f;
        uint4 pE2 = make_uint4(0, 0, 0, 0), pF2 = pE2;
        if (j + 2 < je) {
            int s = g_ssrc[j + 2];
            if (lane < 4) aE2 = als[s * 4 + lane];
            pE2 = pr[(size_t)s * 32 + lane];
        }
        if (j + 3 < je) {
            int s = g_ssrc[j + 3];
            if (lane < 4) aF2 = als[s * 4 + lane];
            pF2 = pr[(size_t)s * 32 + lane];
        }
        // edge j (always valid)
        {
            float w2 = 0.f;
            if (lane < 4) {
                w2 = __expf(lrelu(aEv + aldl));
                sden += w2;
            }
            float wh2 = __shfl_sync(0xffffffffu, w2, lane >> 3);
            const __half2* ph = (const __half2*)&pE;
#pragma unroll
            for (int q = 0; q < 4; q++) {
                float2 f = __half22float2(ph[q]);
                o[2 * q]     = fmaf(wh2, f.x, o[2 * q]);
                o[2 * q + 1] = fmaf(wh2, f.y, o[2 * q + 1]);
            }
        }
        // edge j+1 (warp-uniform guard)
        if (j + 1 < je) {
            float w3 = 0.f;
            if (lane < 4) {
                w3 = __expf(lrelu(aFv + aldl));
                sden += w3;
            }
            float wh3 = __shfl_sync(0xffffffffu, w3, lane >> 3);
            const __half2* ph = (const __half2*)&pF;
#pragma unroll
            for (int q = 0; q < 4; q++) {
                float2 f = __half22float2(ph[q]);
                o[2 * q]     = fmaf(wh3, f.x, o[2 * q]);
                o[2 * q + 1] = fmaf(wh3, f.y, o[2 * q + 1]);
            }
        }
        aEv = aE2; pE = pE2;
        aFv = aF2; pF = pF2;
    }
    float inv = 1.0f / __shfl_sync(0xffffffffu, sden, lane >> 3);
    float4 b0 = ((const float4*)bias)[lane * 2];
    float4 b1 = ((const float4*)bias)[lane * 2 + 1];
    o[0] = o[0] * inv + b0.x; o[1] = o[1] * inv + b0.y;
    o[2] = o[2] * inv + b0.z; o[3] = o[3] * inv + b0.w;
    o[4] = o[4] * inv + b1.x; o[5] = o[5] * inv + b1.y;
    o[6] = o[6] * inv + b1.z; o[7] = o[7] * inv + b1.w;
    if (reshi) {
        uint4 rh = *(const uint4*)(reshi + (size_t)d * 256 + lane * 8);
        uint4 rl = *(const uint4*)(reslo + (size_t)d * 256 + lane * 8);
        const __nv_bfloat162* h2 = (const __nv_bfloat162*)&rh;
        const __nv_bfloat162* l2 = (const __nv_bfloat162*)&rl;
#pragma unroll
        for (int q = 0; q < 4; q++) {
            float2 hf = __bfloat1622float2(h2[q]);
            float2 lf = __bfloat1622float2(l2[q]);
            o[2 * q]     += hf.x + lf.x;
            o[2 * q + 1] += hf.y + lf.y;
        }
    }
    __nv_bfloat162 hv[4], lv[4];
#pragma unroll
    for (int q = 0; q < 4; q++) {
        __nv_bfloat16 h0b = __float2bfloat16(o[2 * q]);
        __nv_bfloat16 h1b = __float2bfloat16(o[2 * q + 1]);
        hv[q] = __nv_bfloat162(h0b, h1b);
        lv[q] = __nv_bfloat162(__float2bfloat16(o[2 * q] - __bfloat162float(h0b)),
                               __float2bfloat16(o[2 * q + 1] - __bfloat162float(h1b)));
    }
    *(uint4*)(hi + (size_t)d * 256 + lane * 8) = *(uint4*)hv;
    *(uint4*)(lo + (size_t)d * 256 + lane * 8) = *(uint4*)lv;
}

// ---------------- fused CSR aggregation, H=1, 128 ch (layer 2, full) --------------
// 2-edge unrolled pipeline. proj row = [h (128) | lin (128)] fp16.
__global__ void gat_agg128(const __half* __restrict__ proj,
                           const float* __restrict__ als, const float* __restrict__ ald,
                           const float* __restrict__ bias, const float* __restrict__ bias2,
                           float* __restrict__ outp) {
    int w = (blockIdx.x * blockDim.x + threadIdx.x) >> 5;
    if (w >= NN) return;
    const int lane = threadIdx.x & 31;
    const int d = w;
    const float aldv = __shfl_sync(0xffffffffu, (lane == 0) ? ald[d] : 0.f, 0);

    float wt = 0.f, sden = 0.f;
    if (lane == 0) {
        wt = __expf(lrelu(als[d] + aldv));
        sden = wt;
    }
    float wh = __shfl_sync(0xffffffffu, wt, 0);
    const uint2* pr = (const uint2*)proj;      // 64 uint2 per row (256 halfs)
    float a0x, a0y, a0z, a0w;
    {
        uint2 pv = pr[(size_t)d * 64 + lane];
        float2 f0 = __half22float2(((const __half2*)&pv)[0]);
        float2 f1 = __half22float2(((const __half2*)&pv)[1]);
        a0x = wh * f0.x; a0y = wh * f0.y; a0z = wh * f1.x; a0w = wh * f1.y;
    }
    const int jb = g_rowptr[d], je = g_rowptr[d + 1];
    float aEv = 0.f, aFv = 0.f;
    uint2 pE = make_uint2(0, 0), pF = pE;
    if (jb < je) {
        int s = g_ssrc[jb];
        if (lane == 0) aEv = als[s];
        pE = pr[(size_t)s * 64 + lane];
    }
    if (jb + 1 < je) {
        int s = g_ssrc[jb + 1];
        if (lane == 0) aFv = als[s];
        pF = pr[(size_t)s * 64 + lane];
    }
    for (int j = jb; j < je; j += 2) {
        float aE2 = 0.f, aF2 = 0.f;
        uint2 pE2 = make_uint2(0, 0), pF2 = pE2;
        if (j + 2 < je) {
            int s = g_ssrc[j + 2];
            if (lane == 0) aE2 = als[s];
            pE2 = pr[(size_t)s * 64 + lane];
        }
        if (j + 3 < je) {
            int s = g_ssrc[j + 3];
            if (lane == 0) aF2 = als[s];
            pF2 = pr[(size_t)s * 64 + lane];
        }
        {
            float w2 = 0.f;
            if (lane == 0) {
                w2 = __expf(lrelu(aEv + aldv));
                sden += w2;
            }
            float wh2 = __shfl_sync(0xffffffffu, w2, 0);
            float2 f0 = __half22float2(((const __half2*)&pE)[0]);
            float2 f1 = __half22float2(((const __half2*)&pE)[1]);
            a0x = fmaf(wh2, f0.x, a0x); a0y = fmaf(wh2, f0.y, a0y);
            a0z = fmaf(wh2, f1.x, a0z); a0w = fmaf(wh2, f1.y, a0w);
        }
        if (j + 1 < je) {
            float w3 = 0.f;
            if (lane == 0) {
                w3 = __expf(lrelu(aFv + aldv));
                sden += w3;
            }
            float wh3 = __shfl_sync(0xffffffffu, w3, 0);
            float2 f0 = __half22float2(((const __half2*)&pF)[0]);
            float2 f1 = __half22float2(((const __half2*)&pF)[1]);
            a0x = fmaf(wh3, f0.x, a0x); a0y = fmaf(wh3, f0.y, a0y);
            a0z = fmaf(wh3, f1.x, a0z); a0w = fmaf(wh3, f1.y, a0w);
        }
        aEv = aE2; pE = pE2;
        aFv = aF2; pF = pF2;
    }
    float inv = 1.0f / __shfl_sync(0xffffffffu, sden, 0);
    float4 b0 = ((const float4*)bias)[lane];
    float4 b2 = ((const float4*)bias2)[lane];
    uint2 lv = pr[(size_t)d * 64 + 32 + lane];   // lin = cols 128..255
    float2 l0 = __half22float2(((const __half2*)&lv)[0]);
    float2 l1 = __half22float2(((const __half2*)&lv)[1]);
    float4 o = make_float4(a0x * inv + b0.x + b2.x + l0.x,
                           a0y * inv + b0.y + b2.y + l0.y,
                           a0z * inv + b0.z + b2.z + l1.x,
                           a0w * inv + b0.w + b2.w + l1.y);
    ((float4*)outp)[(size_t)d * 32 + lane] = o;
}

// ---------------- host orchestration ----------------
extern "C" void kernel_launch(void* const* d_in, const int* in_sizes, int n_in,
                              void* d_out, int out_size) {
    const float* x   = (const float*)d_in[0];
    const void*  ei  = d_in[1];
    const float* W0  = (const float*)d_in[2];
    const float* as0 = (const float*)d_in[3];
    const float* ad0 = (const float*)d_in[4];
    const float* b0  = (const float*)d_in[5];
    const float* W1  = (const float*)d_in[6];
    const float* as1 = (const float*)d_in[7];
    const float* ad1 = (const float*)d_in[8];
    const float* b1  = (const float*)d_in[9];
    const float* W2  = (const float*)d_in[10];
    const float* as2 = (const float*)d_in[11];
    const float* ad2 = (const float*)d_in[12];
    const float* b2  = (const float*)d_in[13];
    const float* Wl  = (const float*)d_in[14];
    const float* bl  = (const float*)d_in[15];
    float* out = (float*)d_out;
    const int E = in_sizes[1] / 2;

    __half *pA, *pB;
    float *alsA, *aldA, *alsB, *aldB, *als2, *ald2;
    int *p_cnt;
    __nv_bfloat16 *p_ahi, *p_alo, *p_w0hi, *p_w0lo, *p_w1hi, *p_w1lo, *p_wchi, *p_wclo;
    cudaGetSymbolAddress((void**)&pA,    g_projA);
    cudaGetSymbolAddress((void**)&pB,    g_projB);
    cudaGetSymbolAddress((void**)&alsA,  g_alsA);
    cudaGetSymbolAddress((void**)&aldA,  g_aldA);
    cudaGetSymbolAddress((void**)&alsB,  g_alsB);
    cudaGetSymbolAddress((void**)&aldB,  g_aldB);
    cudaGetSymbolAddress((void**)&als2,  g_als2);
    cudaGetSymbolAddress((void**)&ald2,  g_ald2);
    cudaGetSymbolAddress((void**)&p_cnt, g_cnt);
    cudaGetSymbolAddress((void**)&p_ahi, g_ahi);
    cudaGetSymbolAddress((void**)&p_alo, g_alo);
    cudaGetSymbolAddress((void**)&p_w0hi, g_w0hi);
    cudaGetSymbolAddress((void**)&p_w0lo, g_w0lo);
    cudaGetSymbolAddress((void**)&p_w1hi, g_w1hi);
    cudaGetSymbolAddress((void**)&p_w1lo, g_w1lo);
    cudaGetSymbolAddress((void**)&p_wchi, g_wchi);
    cudaGetSymbolAddress((void**)&p_wclo, g_wclo);

    constexpr int GEMM_SMEM = 2 * STG + 1024;
    cudaFuncSetAttribute((const void*)gemm_mma,
                         cudaFuncAttributeMaxDynamicSharedMemorySize, GEMM_SMEM);

    cudaStream_t sE;
    cudaStreamCreateWithFlags(&sE, cudaStreamNonBlocking);
    cudaEvent_t evFork, evCSR, evG0, evG1h1, evG1h2, evG2h2;
    cudaEventCreateWithFlags(&evFork, cudaEventDisableTiming);
    cudaEventCreateWithFlags(&evCSR,  cudaEventDisableTiming);
    cudaEventCreateWithFlags(&evG0,   cudaEventDisableTiming);
    cudaEventCreateWithFlags(&evG1h1, cudaEventDisableTiming);
    cudaEventCreateWithFlags(&evG1h2, cudaEventDisableTiming);
    cudaEventCreateWithFlags(&evG2h2, cudaEventDisableTiming);

    cudaMemsetAsync(als2, 0, NN * sizeof(float));
    cudaMemsetAsync(ald2, 0, NN * sizeof(float));
    cudaEventRecord(evFork, 0);

    // ---- S1: CSR build ----
    cudaStreamWaitEvent(sE, evFork, 0);
    probe_kernel<<<1, 256, 0, sE>>>((const int*)ei, E > 4096 ? 4096 : E);
    cudaMemsetAsync(p_cnt, 0, NN * sizeof(int), sE);
    convert_hist<<<(E + 255) / 256, 256, 0, sE>>>(ei, E);
    scanA<<<NB_SCAN, 256, 0, sE>>>();
    scanB<<<1, 256, 0, sE>>>(NB_SCAN);
    scanC<<<NB_SCAN, 256, 0, sE>>>();
    scatter_kernel<<<(E + 255) / 256, 256, 0, sE>>>(E);
    cudaEventRecord(evCSR, sE);

    const int total4 = NN * KDIM / 4;
    const int AGG_B1 = (NH1 * 32 + 255) / 256;
    const int AGG_B2 = (NH2 * 32 + 255) / 256;
    const int AGG_FULL = (NN * 32 + 255) / 256;

    // ---- S0: prep + gemm0 (full) ----
    split_act<<<(total4 + 255) / 256, 256>>>(x, p_ahi, p_alo, total4);
    wsplit_all<<<768, 256>>>(W0, W1, W2, Wl);
    gemm_mma<<<dim3(BX1 + BX2, 4), 256, GEMM_SMEM>>>(p_ahi, p_alo, p_w0hi, p_w0lo,
                                                     pA, NN, HC, 1, as0, ad0, alsA, aldA, 0);
    cudaEventRecord(evG0, 0);

    // ---- layer 0 agg, split halves (no residual; writes layer-0 split) ----
    cudaStreamWaitEvent(0, evCSR, 0);
    gat_agg256<<<AGG_B1, 256>>>(pA, alsA, aldA, b0, nullptr, nullptr,
                                p_ahi, p_alo, 0, NH1);
    cudaStreamWaitEvent(sE, evG0, 0);
    gat_agg256<<<AGG_B2, 256, 0, sE>>>(pA, alsA, aldA, b0, nullptr, nullptr,
                                       p_ahi, p_alo, NH1, NH2);

    // ---- layer 1 GEMM, split halves (h1 on S0 overlaps agg0_h2 on S1) ----
    gemm_mma<<<dim3(BX1, 4), 256, GEMM_SMEM>>>(p_ahi, p_alo, p_w1hi, p_w1lo,
                                               pB, NN, HC, 1, as1, ad1, alsB, aldB, 0);
    cudaEventRecord(evG1h1, 0);
    gemm_mma<<<dim3(BX2, 4), 256, GEMM_SMEM, sE>>>(p_ahi, p_alo, p_w1hi, p_w1lo,
                                                   pB, NN, HC, 1, as1, ad1, alsB, aldB, BX1);
    cudaEventRecord(evG1h2, sE);

    // ---- layer 1 agg, split halves (residual = reconstructed layer-0 split) ----
    cudaStreamWaitEvent(0, evG1h2, 0);
    gat_agg256<<<AGG_B1, 256>>>(pB, alsB, aldB, b1, p_ahi, p_alo,
                                p_ahi, p_alo, 0, NH1);
    cudaStreamWaitEvent(sE, evG1h1, 0);
    gat_agg256<<<AGG_B2, 256, 0, sE>>>(pB, alsB, aldB, b1, p_ahi, p_alo,
                                       p_ahi, p_alo, NH1, NH2);

    // ---- layer 2 GEMM, split halves (h1 on S0 overlaps agg1_h2 on S1) ----
    gemm_mma<<<dim3(BX1, 4), 256, GEMM_SMEM>>>(p_ahi, p_alo, p_wchi, p_wclo,
                                               pA, NN, 256, 2, as2, ad2, als2, ald2, 0);
    gemm_mma<<<dim3(BX2, 4), 256, GEMM_SMEM, sE>>>(p_ahi, p_alo, p_wchi, p_wclo,
                                                   pA, NN, 256, 2, as2, ad2, als2, ald2, BX1);
    cudaEventRecord(evG2h2, sE);

    // ---- layer 2 agg (full) ----
    cudaStreamWaitEvent(0, evG2h2, 0);
    gat_agg128<<<AGG_FULL, 256>>>(pA, als2, ald2, b2, bl, out);

    cudaEventDestroy(evFork);
    cudaEventDestroy(evCSR);
    cudaEventDestroy(evG0);
    cudaEventDestroy(evG1h1);
    cudaEventDestroy(evG1h2);
    cudaEventDestroy(evG2h2);
    cudaStreamDestroy(sE);
}

// round 17
// speedup vs baseline: 1.1033x; 1.1033x over previous
#include <cuda_runtime.h>
#include <cuda_bf16.h>
#include <cuda_fp16.h>
#include <cstdint>

// ---------------- constants ----------------
#define NN      50000
#define MAXE    2000000
#define HEADS   4
#define HC      256          // HEADS*HID
#define OUTC    128
#define KDIM    256
#define NB_SCAN ((NN + 255) / 256)
// half-split at a 128-row boundary
#define NH1     25088
#define NH2     (NN - NH1)        // 24912
#define BX1     (NH1 / 128)       // 196
#define BX2     ((NN + 127) / 128 - BX1)  // 195

// ---------------- device scratch ----------------
__device__ __half   g_projA[(size_t)NN * HC];
__device__ __half   g_projB[(size_t)NN * HC];
__device__ float    g_alsA[NN * HEADS], g_aldA[NN * HEADS];
__device__ float    g_alsB[NN * HEADS], g_aldB[NN * HEADS];
__device__ float    g_als2[NN],         g_ald2[NN];
__device__ int      g_src [MAXE];
__device__ int      g_dst [MAXE];
__device__ int      g_ssrc[MAXE];
__device__ int      g_cnt [NN];
__device__ int      g_tmp [NN];
__device__ int      g_bsum[256];
__device__ int      g_boff[256];
__device__ int      g_cursor[NN];
__device__ int      g_rowptr[NN + 1];
__device__ int      g_is64;
__device__ __nv_bfloat16 g_ahi[(size_t)NN * KDIM];
__device__ __nv_bfloat16 g_alo[(size_t)NN * KDIM];
__device__ __nv_bfloat16 g_w0hi[KDIM * HC],  g_w0lo[KDIM * HC];
__device__ __nv_bfloat16 g_w1hi[KDIM * HC],  g_w1lo[KDIM * HC];
__device__ __nv_bfloat16 g_wchi[KDIM * 256], g_wclo[KDIM * 256];  // [W2 | Wl]

// ---------------- helpers ----------------
__device__ __forceinline__ float lrelu(float v) { return v > 0.f ? v : 0.2f * v; }

__device__ __forceinline__ uint32_t s2u(const void* p) {
    uint32_t a;
    asm("{ .reg .u64 t; cvta.to.shared.u64 t, %1; cvt.u32.u64 %0, t; }" : "=r"(a) : "l"(p));
    return a;
}

__device__ __forceinline__ void cpa16(uint32_t dst, const void* src, int ssize) {
    asm volatile("cp.async.cg.shared.global [%0], [%1], 16, %2;"
                 :: "r"(dst), "l"(src), "r"(ssize));
}

#define LDM4(d, addr) \
    asm volatile("ldmatrix.sync.aligned.m8n8.x4.shared.b16 {%0,%1,%2,%3}, [%4];" \
        : "=r"((d)[0]), "=r"((d)[1]), "=r"((d)[2]), "=r"((d)[3]) : "r"(addr))

#define MMA_BF16(c, a, b0, b1) \
    asm volatile("mma.sync.aligned.m16n8k16.row.col.f32.bf16.bf16.f32 " \
        "{%0,%1,%2,%3}, {%4,%5,%6,%7}, {%8,%9}, {%0,%1,%2,%3};" \
        : "+f"((c)[0]), "+f"((c)[1]), "+f"((c)[2]), "+f"((c)[3]) \
        : "r"((a)[0]), "r"((a)[1]), "r"((a)[2]), "r"((a)[3]), "r"(b0), "r"(b1))

// ---------------- edge index prep ----------------
__global__ void probe_kernel(const int* p32, int nchk) {
    __shared__ int cnt;
    if (threadIdx.x == 0) cnt = 0;
    __syncthreads();
    int z = 0;
    for (int k = threadIdx.x; k < nchk; k += 256)
        if (p32[2 * k + 1] == 0) z++;
    atomicAdd(&cnt, z);
    __syncthreads();
    if (threadIdx.x == 0) g_is64 = (cnt * 2 > nchk) ? 1 : 0;
}

__global__ void convert_hist(const void* ei, int E) {
    int e = blockIdx.x * blockDim.x + threadIdx.x;
    if (e >= E || e >= MAXE) return;
    int s, d;
    if (g_is64) {
        const long long* p = (const long long*)ei;
        s = (int)p[e];
        d = (int)p[(size_t)E + e];
    } else {
        const int* p = (const int*)ei;
        s = p[e];
        d = p[E + e];
    }
    g_src[e] = s;
    g_dst[e] = d;
    atomicAdd(&g_cnt[d], 1);
}

// ---------------- 3-phase exclusive scan ----------------
__global__ void scanA() {
    int i = blockIdx.x * 256 + threadIdx.x;
    int lane = threadIdx.x & 31, warp = threadIdx.x >> 5;
    int v = (i < NN) ? g_cnt[i] : 0;
    int x = v;
#pragma unroll
    for (int off = 1; off < 32; off <<= 1) {
        int t = __shfl_up_sync(0xffffffffu, x, off);
        if (lane >= off) x += t;
    }
    __shared__ int ws[8];
    if (lane == 31) ws[warp] = x;
    __syncthreads();
    if (threadIdx.x == 0) {
        int run = 0;
#pragma unroll
        for (int j = 0; j < 8; j++) { int t = ws[j]; ws[j] = run; run += t; }
        g_bsum[blockIdx.x] = run;
    }
    __syncthreads();
    if (i < NN) g_tmp[i] = x - v + ws[warp];
}

__global__ void scanB(int nb) {
    int tid = threadIdx.x, lane = tid & 31, warp = tid >> 5;
    int v = (tid < nb) ? g_bsum[tid] : 0;
    int x = v;
#pragma unroll
    for (int off = 1; off < 32; off <<= 1) {
        int t = __shfl_up_sync(0xffffffffu, x, off);
        if (lane >= off) x += t;
    }
    __shared__ int ws[8];
    if (lane == 31) ws[warp] = x;
    __syncthreads();
    if (tid == 0) {
        int run = 0;
#pragma unroll
        for (int j = 0; j < 8; j++) { int t = ws[j]; ws[j] = run; run += t; }
        g_rowptr[NN] = run;
    }
    __syncthreads();
    g_boff[tid] = x - v + ws[warp];
}

__global__ void scanC() {
    int i = blockIdx.x * 256 + threadIdx.x;
    if (i < NN) {
        int r = g_tmp[i] + g_boff[blockIdx.x];
        g_rowptr[i] = r;
        g_cursor[i] = r;
    }
}

__global__ void scatter_kernel(int E) {
    int e = blockIdx.x * blockDim.x + threadIdx.x;
    if (e >= E || e >= MAXE) return;
    int pos = atomicAdd(&g_cursor[g_dst[e]], 1);
    g_ssrc[pos] = g_src[e];
}

// ---------------- bf16 hi/lo split (layer-0 input only) ----------------
__global__ void split_act(const float* __restrict__ in, __nv_bfloat16* __restrict__ hi,
                          __nv_bfloat16* __restrict__ lo, int total4) {
    int i = blockIdx.x * blockDim.x + threadIdx.x;
    if (i >= total4) return;
    float4 v = ((const float4*)in)[i];
    float vv[4] = {v.x, v.y, v.z, v.w};
    __nv_bfloat16 h[4], l[4];
#pragma unroll
    for (int j = 0; j < 4; j++) {
        h[j] = __float2bfloat16(vv[j]);
        l[j] = __float2bfloat16(vv[j] - __bfloat162float(h[j]));
    }
    ((__nv_bfloat162*)hi)[2 * i]     = __nv_bfloat162(h[0], h[1]);
    ((__nv_bfloat162*)hi)[2 * i + 1] = __nv_bfloat162(h[2], h[3]);
    ((__nv_bfloat162*)lo)[2 * i]     = __nv_bfloat162(l[0], l[1]);
    ((__nv_bfloat162*)lo)[2 * i + 1] = __nv_bfloat162(l[2], l[3]);
}

// ---------------- merged weight transpose + split ----------------
__global__ void wsplit_all(const float* __restrict__ W0, const float* __restrict__ W1,
                           const float* __restrict__ W2, const float* __restrict__ Wl) {
    int idx = blockIdx.x * blockDim.x + threadIdx.x;
    if (idx >= 196608) return;
    const float* W;
    __nv_bfloat16 *hi, *lo;
    int local, Nn;
    if (idx < 65536)       { W = W0; hi = g_w0hi; lo = g_w0lo; local = idx; Nn = 256; }
    else if (idx < 131072) { W = W1; hi = g_w1hi; lo = g_w1lo; local = idx - 65536; Nn = 256; }
    else if (idx < 163840) { W = W2; hi = g_wchi; lo = g_wclo; local = idx - 131072; Nn = 128; }
    else                   { W = Wl; hi = g_wchi + 128 * 256; lo = g_wclo + 128 * 256;
                             local = idx - 163840; Nn = 128; }
    int n = local >> 8, k = local & 255;
    float v = W[(size_t)k * Nn + n];
    __nv_bfloat16 h = __float2bfloat16(v);
    hi[local] = h;
    lo[local] = __float2bfloat16(v - __bfloat162float(h));
}

// ---------------- HMMA split-bf16 GEMM, 2-stage cp.async pipeline ----------------
// Output C is fp16 (gather buffer); attention logits use the fp32 accumulators.
#define STG 43008
__global__ void __launch_bounds__(256, 2) gemm_mma(
    const __nv_bfloat16* __restrict__ Ahi, const __nv_bfloat16* __restrict__ Alo,
    const __nv_bfloat16* __restrict__ Bhi, const __nv_bfloat16* __restrict__ Blo,
    __half* __restrict__ C, int M, int Nn,
    int lmode, const float* __restrict__ a_s, const float* __restrict__ a_d,
    float* __restrict__ als, float* __restrict__ ald, int bx0)
{
    extern __shared__ __align__(16) char smem[];
    float* red_ss = (float*)(smem + 2 * STG);
    float* red_sd = red_ss + 128;
    constexpr int A_HI = 0;
    constexpr int A_LO = 14336;
    constexpr int B_HI = 28672;
    constexpr int B_LO = 35840;

    const int tid  = threadIdx.x;
    const int lane = tid & 31;
    const int wid  = tid >> 5;
    const int warpRow = wid & 3;
    const int warpCol = wid >> 2;
    const int rowBase = (blockIdx.x + bx0) * 128;
    const int colBase = blockIdx.y * 64;

    float acc[2][4][4];
#pragma unroll
    for (int i = 0; i < 2; i++)
#pragma unroll
        for (int j = 0; j < 4; j++)
#pragma unroll
            for (int q = 0; q < 4; q++) acc[i][j][q] = 0.f;

    const uint32_t sb = s2u(smem);
    uint32_t aAdrH[2], aAdrL[2];
#pragma unroll
    for (int m16 = 0; m16 < 2; m16++) {
        uint32_t r = warpRow * 32 + m16 * 16 + (lane & 15);
        uint32_t cb = ((lane >> 4) * 8) * 2;
        aAdrH[m16] = sb + A_HI + r * 112 + cb;
        aAdrL[m16] = sb + A_LO + r * 112 + cb;
    }
    uint32_t bAdrH[2], bAdrL[2];
#pragma unroll
    for (int nbp = 0; nbp < 2; nbp++) {
        uint32_t r = warpCol * 32 + nbp * 16 + ((lane >> 4) << 3) + (lane & 7);
        uint32_t cb = (((lane >> 3) & 1) * 8) * 2;
        bAdrH[nbp] = sb + B_HI + r * 112 + cb;
        bAdrL[nbp] = sb + B_LO + r * 112 + cb;
    }

    const int ar0 = tid >> 2, aseg = tid & 3;
    const int br0 = tid >> 2;

    auto prefetch = [&](int c) {
        const uint32_t base = sb + (uint32_t)(c & 1) * STG;
        const int k0 = c * 32;
#pragma unroll
        for (int it = 0; it < 2; it++) {
            int r = ar0 + it * 64;
            int gr = rowBase + r;
            int ok = (gr < M) ? 16 : 0;
            size_t g = (size_t)(ok ? gr : 0) * KDIM + k0 + aseg * 8;
            cpa16(base + A_HI + r * 112 + aseg * 16, Ahi + g, ok);
            cpa16(base + A_LO + r * 112 + aseg * 16, Alo + g, ok);
        }
        {
            size_t g = (size_t)(colBase + br0) * KDIM + k0 + aseg * 8;
            cpa16(base + B_HI + br0 * 112 + aseg * 16, Bhi + g, 16);
            cpa16(base + B_LO + br0 * 112 + aseg * 16, Blo + g, 16);
        }
        asm volatile("cp.async.commit_group;");
    };

    prefetch(0);
    for (int c = 0; c < 8; c++) {
        if (c < 7) {
            prefetch(c + 1);
            asm volatile("cp.async.wait_group 1;");
        } else {
            asm volatile("cp.async.wait_group 0;");
        }
        __syncthreads();
        const uint32_t so = (uint32_t)(c & 1) * STG;
#pragma unroll
        for (int kk = 0; kk < 2; kk++) {
            const uint32_t kb = so + kk * 32;
            uint32_t ah[2][4], al[2][4], bh[2][4], bl[2][4];
            LDM4(ah[0], aAdrH[0] + kb);
            LDM4(ah[1], aAdrH[1] + kb);
            LDM4(al[0], aAdrL[0] + kb);
            LDM4(al[1], aAdrL[1] + kb);
            LDM4(bh[0], bAdrH[0] + kb);
            LDM4(bh[1], bAdrH[1] + kb);
            LDM4(bl[0], bAdrL[0] + kb);
            LDM4(bl[1], bAdrL[1] + kb);
#pragma unroll
            for (int m16 = 0; m16 < 2; m16++) {
#pragma unroll
                for (int nb = 0; nb < 4; nb++) {
                    const int p = nb >> 1, q = (nb & 1) * 2;
                    MMA_BF16(acc[m16][nb], ah[m16], bh[p][q], bh[p][q + 1]);
                    MMA_BF16(acc[m16][nb], ah[m16], bl[p][q], bl[p][q + 1]);
                    MMA_BF16(acc[m16][nb], al[m16], bh[p][q], bh[p][q + 1]);
                }
            }
        }
        __syncthreads();
    }

    // ---- store C (fp16) ----
#pragma unroll
    for (int m16 = 0; m16 < 2; m16++) {
        int r0 = rowBase + warpRow * 32 + m16 * 16 + (lane >> 2);
#pragma unroll
        for (int nb = 0; nb < 4; nb++) {
            int col = colBase + warpCol * 32 + nb * 8 + (lane & 3) * 2;
            if (r0 < M)
                *(__half2*)(C + (size_t)r0 * Nn + col) =
                    __floats2half2_rn(acc[m16][nb][0], acc[m16][nb][1]);
            if (r0 + 8 < M)
                *(__half2*)(C + (size_t)(r0 + 8) * Nn + col) =
                    __floats2half2_rn(acc[m16][nb][2], acc[m16][nb][3]);
        }
    }

    // ---- fused attention logits (from fp32 accumulators; exact) ----
    if (lmode == 1 || (lmode == 2 && blockIdx.y < 2)) {
        const int y = blockIdx.y;
        float pss[2][2] = {{0.f, 0.f}, {0.f, 0.f}};
        float psd[2][2] = {{0.f, 0.f}, {0.f, 0.f}};
#pragma unroll
        for (int m16 = 0; m16 < 2; m16++) {
#pragma unroll
            for (int nb = 0; nb < 4; nb++) {
                int cl = warpCol * 32 + nb * 8 + (lane & 3) * 2;
                float s0 = __ldg(a_s + y * 64 + cl), s1 = __ldg(a_s + y * 64 + cl + 1);
                float d0 = __ldg(a_d + y * 64 + cl), d1 = __ldg(a_d + y * 64 + cl + 1);
                pss[m16][0] += acc[m16][nb][0] * s0 + acc[m16][nb][1] * s1;
                psd[m16][0] += acc[m16][nb][0] * d0 + acc[m16][nb][1] * d1;
                pss[m16][1] += acc[m16][nb][2] * s0 + acc[m16][nb][3] * s1;
                psd[m16][1] += acc[m16][nb][2] * d0 + acc[m16][nb][3] * d1;
            }
        }
#pragma unroll
        for (int m16 = 0; m16 < 2; m16++)
#pragma unroll
            for (int hh = 0; hh < 2; hh++) {
                pss[m16][hh] += __shfl_xor_sync(0xffffffffu, pss[m16][hh], 1);
                pss[m16][hh] += __shfl_xor_sync(0xffffffffu, pss[m16][hh], 2);
                psd[m16][hh] += __shfl_xor_sync(0xffffffffu, psd[m16][hh], 1);
                psd[m16][hh] += __shfl_xor_sync(0xffffffffu, psd[m16][hh], 2);
            }
        if (warpCol == 0 && (lane & 3) == 0) {
#pragma unroll
            for (int m16 = 0; m16 < 2; m16++)
#pragma unroll
                for (int hh = 0; hh < 2; hh++) {
                    int rb = warpRow * 32 + m16 * 16 + hh * 8 + (lane >> 2);
                    red_ss[rb] = pss[m16][hh];
                    red_sd[rb] = psd[m16][hh];
                }
        }
        __syncthreads();
        if (warpCol == 1 && (lane & 3) == 0) {
#pragma unroll
            for (int m16 = 0; m16 < 2; m16++)
#pragma unroll
                for (int hh = 0; hh < 2; hh++) {
                    int rb = warpRow * 32 + m16 * 16 + hh * 8 + (lane >> 2);
                    int row = rowBase + rb;
                    if (row < M) {
                        float S = red_ss[rb] + pss[m16][hh];
                        float D = red_sd[rb] + psd[m16][hh];
                        if (lmode == 1) {
                            als[row * 4 + y] = S;
                            ald[row * 4 + y] = D;
                        } else {
                            atomicAdd(&als[row], S);
                            atomicAdd(&ald[row], D);
                        }
                    }
                }
        }
    }
}

// ---------------- fused CSR aggregation, H=4, 256 ch: warp per dst (range) --------
// Depth-1 software pipeline; per-lane redundant exp (no SHFL in the edge chain).
__global__ void gat_agg256(const __half* __restrict__ proj,
                           const float* __restrict__ als, const float* __restrict__ ald,
                           const float* __restrict__ bias,
                           const __nv_bfloat16* __restrict__ reshi,
                           const __nv_bfloat16* __restrict__ reslo,
                           __nv_bfloat16* __restrict__ hi, __nv_bfloat16* __restrict__ lo,
                           int d0, int nd) {
    int w = (blockIdx.x * blockDim.x + threadIdx.x) >> 5;
    if (w >= nd) return;
    const int lane = threadIdx.x & 31;
    const int hh8 = lane >> 3;                 // head owned by this lane
    const int d = d0 + w;
    const float aldl = ald[d * 4 + hh8];

    // self-loop weight, computed per lane (redundant within 8-lane head group)
    float wh = __expf(lrelu(als[d * 4 + hh8] + aldl));
    float sden = wh;

    const uint4* pr = (const uint4*)proj;      // 32 uint4 per row (256 halfs)
    float o[8];
    {
        uint4 pv = pr[(size_t)d * 32 + lane];
        const __half2* ph = (const __half2*)&pv;
#pragma unroll
        for (int q = 0; q < 4; q++) {
            float2 f = __half22float2(ph[q]);
            o[2 * q]     = wh * f.x;
            o[2 * q + 1] = wh * f.y;
        }
    }
    const int jb = g_rowptr[d], je = g_rowptr[d + 1];
    // depth-1 pipeline prologue
    float alsv = 0.f;
    uint4 pv   = make_uint4(0, 0, 0, 0);
    if (jb < je) {
        int s = g_ssrc[jb];
        alsv = als[s * 4 + hh8];
        pv = pr[(size_t)s * 32 + lane];
    }
    for (int j = jb; j < je; j++) {
        // prefetch next iteration's operands
        float alsn = 0.f;
        uint4 pn   = make_uint4(0, 0, 0, 0);
        if (j + 1 < je) {
            int sn = g_ssrc[j + 1];
            alsn = als[sn * 4 + hh8];
            pn = pr[(size_t)sn * 32 + lane];
        }
        // current iteration: per-lane exp, no shuffle
        float wh2 = __expf(lrelu(alsv + aldl));
        sden += wh2;
        const __half2* ph = (const __half2*)&pv;
#pragma unroll
        for (int q = 0; q < 4; q++) {
            float2 f = __half22float2(ph[q]);
            o[2 * q]     = fmaf(wh2, f.x, o[2 * q]);
            o[2 * q + 1] = fmaf(wh2, f.y, o[2 * q + 1]);
        }
        alsv = alsn; pv = pn;
    }
    float inv = 1.0f / sden;                   // per-lane; identical within head group
    float4 b0 = ((const float4*)bias)[lane * 2];
    float4 b1 = ((const float4*)bias)[lane * 2 + 1];
    o[0] = o[0] * inv + b0.x; o[1] = o[1] * inv + b0.y;
    o[2] = o[2] * inv + b0.z; o[3] = o[3] * inv + b0.w;
    o[4] = o[4] * inv + b1.x; o[5] = o[5] * inv + b1.y;
    o[6] = o[6] * inv + b1.z; o[7] = o[7] * inv + b1.w;
    if (reshi) {
        uint4 rh = *(const uint4*)(reshi + (size_t)d * 256 + lane * 8);
        uint4 rl = *(const uint4*)(reslo + (size_t)d * 256 + lane * 8);
        const __nv_bfloat162* h2 = (const __nv_bfloat162*)&rh;
        const __nv_bfloat162* l2 = (const __nv_bfloat162*)&rl;
#pragma unroll
        for (int q = 0; q < 4; q++) {
            float2 hf = __bfloat1622float2(h2[q]);
            float2 lf = __bfloat1622float2(l2[q]);
            o[2 * q]     += hf.x + lf.x;
            o[2 * q + 1] += hf.y + lf.y;
        }
    }
    __nv_bfloat162 hv[4], lv[4];
#pragma unroll
    for (int q = 0; q < 4; q++) {
        __nv_bfloat16 h0b = __float2bfloat16(o[2 * q]);
        __nv_bfloat16 h1b = __float2bfloat16(o[2 * q + 1]);
        hv[q] = __nv_bfloat162(h0b, h1b);
        lv[q] = __nv_bfloat162(__float2bfloat16(o[2 * q] - __bfloat162float(h0b)),
                               __float2bfloat16(o[2 * q + 1] - __bfloat162float(h1b)));
    }
    *(uint4*)(hi + (size_t)d * 256 + lane * 8) = *(uint4*)hv;
    *(uint4*)(lo + (size_t)d * 256 + lane * 8) = *(uint4*)lv;
}

// ---------------- fused CSR aggregation, H=1, 128 ch (layer 2, full) --------------
// Depth-1 pipeline; per-lane redundant exp (no SHFL). proj row = [h | lin] fp16.
__global__ void gat_agg128(const __half* __restrict__ proj,
                           const float* __restrict__ als, const float* __restrict__ ald,
                           const float* __restrict__ bias, const float* __restrict__ bias2,
                           float* __restrict__ outp) {
    int w = (blockIdx.x * blockDim.x + threadIdx.x) >> 5;
    if (w >= NN) return;
    const int lane = threadIdx.x & 31;
    const int d = w;
    const float aldv = ald[d];                 // all lanes load (broadcast)

    float wh = __expf(lrelu(als[d] + aldv));
    float sden = wh;

    const uint2* pr = (const uint2*)proj;      // 64 uint2 per row (256 halfs)
    float a0x, a0y, a0z, a0w;
    {
        uint2 pv = pr[(size_t)d * 64 + lane];
        float2 f0 = __half22float2(((const __half2*)&pv)[0]);
        float2 f1 = __half22float2(((const __half2*)&pv)[1]);
        a0x = wh * f0.x; a0y = wh * f0.y; a0z = wh * f1.x; a0w = wh * f1.y;
    }
    const int jb = g_rowptr[d], je = g_rowptr[d + 1];
    float alsv = 0.f;
    uint2 pv   = make_uint2(0, 0);
    if (jb < je) {
        int s = g_ssrc[jb];
        alsv = als[s];
        pv = pr[(size_t)s * 64 + lane];
    }
    for (int j = jb; j < je; j++) {
        float alsn = 0.f;
        uint2 pn   = make_uint2(0, 0);
        if (j + 1 < je) {
            int sn = g_ssrc[j + 1];
            alsn = als[sn];
            pn = pr[(size_t)sn * 64 + lane];
        }
        float wh2 = __expf(lrelu(alsv + aldv));
        sden += wh2;
        float2 f0 = __half22float2(((const __half2*)&pv)[0]);
        float2 f1 = __half22float2(((const __half2*)&pv)[1]);
        a0x = fmaf(wh2, f0.x, a0x); a0y = fmaf(wh2, f0.y, a0y);
        a0z = fmaf(wh2, f1.x, a0z); a0w = fmaf(wh2, f1.y, a0w);
        alsv = alsn; pv = pn;
    }
    float inv = 1.0f / sden;
    float4 b0 = ((const float4*)bias)[lane];
    float4 b2 = ((const float4*)bias2)[lane];
    uint2 lv = pr[(size_t)d * 64 + 32 + lane];   // lin = cols 128..255
    float2 l0 = __half22float2(((const __half2*)&lv)[0]);
    float2 l1 = __half22float2(((const __half2*)&lv)[1]);
    float4 o = make_float4(a0x * inv + b0.x + b2.x + l0.x,
                           a0y * inv + b0.y + b2.y + l0.y,
                           a0z * inv + b0.z + b2.z + l1.x,
                           a0w * inv + b0.w + b2.w + l1.y);
    ((float4*)outp)[(size_t)d * 32 + lane] = o;
}

// ---------------- host orchestration ----------------
extern "C" void kernel_launch(void* const* d_in, const int* in_sizes, int n_in,
                              void* d_out, int out_size) {
    const float* x   = (const float*)d_in[0];
    const void*  ei  = d_in[1];
    const float* W0  = (const float*)d_in[2];
    const float* as0 = (const float*)d_in[3];
    const float* ad0 = (const float*)d_in[4];
    const float* b0  = (const float*)d_in[5];
    const float* W1  = (const float*)d_in[6];
    const float* as1 = (const float*)d_in[7];
    const float* ad1 = (const float*)d_in[8];
    const float* b1  = (const float*)d_in[9];
    const float* W2  = (const float*)d_in[10];
    const float* as2 = (const float*)d_in[11];
    const float* ad2 = (const float*)d_in[12];
    const float* b2  = (const float*)d_in[13];
    const float* Wl  = (const float*)d_in[14];
    const float* bl  = (const float*)d_in[15];
    float* out = (float*)d_out;
    const int E = in_sizes[1] / 2;

    __half *pA, *pB;
    float *alsA, *aldA, *alsB, *aldB, *als2, *ald2;
    int *p_cnt;
    __nv_bfloat16 *p_ahi, *p_alo, *p_w0hi, *p_w0lo, *p_w1hi, *p_w1lo, *p_wchi, *p_wclo;
    cudaGetSymbolAddress((void**)&pA,    g_projA);
    cudaGetSymbolAddress((void**)&pB,    g_projB);
    cudaGetSymbolAddress((void**)&alsA,  g_alsA);
    cudaGetSymbolAddress((void**)&aldA,  g_aldA);
    cudaGetSymbolAddress((void**)&alsB,  g_alsB);
    cudaGetSymbolAddress((void**)&aldB,  g_aldB);
    cudaGetSymbolAddress((void**)&als2,  g_als2);
    cudaGetSymbolAddress((void**)&ald2,  g_ald2);
    cudaGetSymbolAddress((void**)&p_cnt, g_cnt);
    cudaGetSymbolAddress((void**)&p_ahi, g_ahi);
    cudaGetSymbolAddress((void**)&p_alo, g_alo);
    cudaGetSymbolAddress((void**)&p_w0hi, g_w0hi);
    cudaGetSymbolAddress((void**)&p_w0lo, g_w0lo);
    cudaGetSymbolAddress((void**)&p_w1hi, g_w1hi);
    cudaGetSymbolAddress((void**)&p_w1lo, g_w1lo);
    cudaGetSymbolAddress((void**)&p_wchi, g_wchi);
    cudaGetSymbolAddress((void**)&p_wclo, g_wclo);

    constexpr int GEMM_SMEM = 2 * STG + 1024;
    cudaFuncSetAttribute((const void*)gemm_mma,
                         cudaFuncAttributeMaxDynamicSharedMemorySize, GEMM_SMEM);

    cudaStream_t sE;
    cudaStreamCreateWithFlags(&sE, cudaStreamNonBlocking);
    cudaEvent_t evFork, evCSR, evG0, evG1h1, evG1h2, evG2h2;
    cudaEventCreateWithFlags(&evFork, cudaEventDisableTiming);
    cudaEventCreateWithFlags(&evCSR,  cudaEventDisableTiming);
    cudaEventCreateWithFlags(&evG0,   cudaEventDisableTiming);
    cudaEventCreateWithFlags(&evG1h1, cudaEventDisableTiming);
    cudaEventCreateWithFlags(&evG1h2, cudaEventDisableTiming);
    cudaEventCreateWithFlags(&evG2h2, cudaEventDisableTiming);

    cudaMemsetAsync(als2, 0, NN * sizeof(float));
    cudaMemsetAsync(ald2, 0, NN * sizeof(float));
    cudaEventRecord(evFork, 0);

    // ---- S1: CSR build ----
    cudaStreamWaitEvent(sE, evFork, 0);
    probe_kernel<<<1, 256, 0, sE>>>((const int*)ei, E > 4096 ? 4096 : E);
    cudaMemsetAsync(p_cnt, 0, NN * sizeof(int), sE);
    convert_hist<<<(E + 255) / 256, 256, 0, sE>>>(ei, E);
    scanA<<<NB_SCAN, 256, 0, sE>>>();
    scanB<<<1, 256, 0, sE>>>(NB_SCAN);
    scanC<<<NB_SCAN, 256, 0, sE>>>();
    scatter_kernel<<<(E + 255) / 256, 256, 0, sE>>>(E);
    cudaEventRecord(evCSR, sE);

    const int total4 = NN * KDIM / 4;
    const int AGG_B1 = (NH1 * 32 + 255) / 256;
    const int AGG_B2 = (NH2 * 32 + 255) / 256;
    const int AGG_FULL = (NN * 32 + 255) / 256;

    // ---- S0: prep + gemm0 (full) ----
    split_act<<<(total4 + 255) / 256, 256>>>(x, p_ahi, p_alo, total4);
    wsplit_all<<<768, 256>>>(W0, W1, W2, Wl);
    gemm_mma<<<dim3(BX1 + BX2, 4), 256, GEMM_SMEM>>>(p_ahi, p_alo, p_w0hi, p_w0lo,
                                                     pA, NN, HC, 1, as0, ad0, alsA, aldA, 0);
    cudaEventRecord(evG0, 0);

    // ---- layer 0 agg, split halves (no residual; writes layer-0 split) ----
    cudaStreamWaitEvent(0, evCSR, 0);
    gat_agg256<<<AGG_B1, 256>>>(pA, alsA, aldA, b0, nullptr, nullptr,
                                p_ahi, p_alo, 0, NH1);
    cudaStreamWaitEvent(sE, evG0, 0);
    gat_agg256<<<AGG_B2, 256, 0, sE>>>(pA, alsA, aldA, b0, nullptr, nullptr,
                                       p_ahi, p_alo, NH1, NH2);

    // ---- layer 1 GEMM, split halves (h1 on S0 overlaps agg0_h2 on S1) ----
    gemm_mma<<<dim3(BX1, 4), 256, GEMM_SMEM>>>(p_ahi, p_alo, p_w1hi, p_w1lo,
                                               pB, NN, HC, 1, as1, ad1, alsB, aldB, 0);
    cudaEventRecord(evG1h1, 0);
    gemm_mma<<<dim3(BX2, 4), 256, GEMM_SMEM, sE>>>(p_ahi, p_alo, p_w1hi, p_w1lo,
                                                   pB, NN, HC, 1, as1, ad1, alsB, aldB, BX1);
    cudaEventRecord(evG1h2, sE);

    // ---- layer 1 agg, split halves (residual = reconstructed layer-0 split) ----
    cudaStreamWaitEvent(0, evG1h2, 0);
    gat_agg256<<<AGG_B1, 256>>>(pB, alsB, aldB, b1, p_ahi, p_alo,
                                p_ahi, p_alo, 0, NH1);
    cudaStreamWaitEvent(sE, evG1h1, 0);
    gat_agg256<<<AGG_B2, 256, 0, sE>>>(pB, alsB, aldB, b1, p_ahi, p_alo,
                                       p_ahi, p_alo, NH1, NH2);

    // ---- layer 2 GEMM, split halves (h1 on S0 overlaps agg1_h2 on S1) ----
    gemm_mma<<<dim3(BX1, 4), 256, GEMM_SMEM>>>(p_ahi, p_alo, p_wchi, p_wclo,
                                               pA, NN, 256, 2, as2, ad2, als2, ald2, 0);
    gemm_mma<<<dim3(BX2, 4), 256, GEMM_SMEM, sE>>>(p_ahi, p_alo, p_wchi, p_wclo,
                                                   pA, NN, 256, 2, as2, ad2, als2, ald2, BX1);
    cudaEventRecord(evG2h2, sE);

    // ---- layer 2 agg (full) ----
    cudaStreamWaitEvent(0, evG2h2, 0);
    gat_agg128<<<AGG_FULL, 256>>>(pA, als2, ald2, b2, bl, out);

    cudaEventDestroy(evFork);
    cudaEventDestroy(evCSR);
    cudaEventDestroy(evG0);
    cudaEventDestroy(evG1h1);
    cudaEventDestroy(evG1h2);
    cudaEventDestroy(evG2h2);
    cudaStreamDestroy(sE);
}